// round 11
// baseline (speedup 1.0000x reference)
#include <cuda_runtime.h>
#include <cstdint>
#include <cstddef>

#define BB   16
#define PP   22536
#define NOBJ 32
#define NCLS 80
#define NROW (BB * PP)                       // 360,576
#define NE4  (NROW * (NCLS / 4))             // 7,211,520 float4 elements

#define OBJ_SPLITS 8
#define OBJ_CHUNK  (PP / OBJ_SPLITS)         // 2817 exactly
#define OBJ_TOT    (BB * NOBJ * OBJ_SPLITS)  // 4096 blocks

#define RS_ITER    5
#define RS_E4      (256 * RS_ITER)           // 1280 e4 per block = 64 rows exactly
#define RS_ROWS    64
#define RS_BLOCKS  (NE4 / RS_E4)             // 5634 exactly

#define MEGA_BLOCKS (OBJ_TOT + RS_BLOCKS)    // 9730
#define NPAIR (BB * NOBJ)                    // 512

// ---------------- persistent device scratch (no allocs allowed) ---------------
__device__ unsigned long long g_obj_part[OBJ_TOT];   // partial keys, idx z*512 + b*32 + o
__device__ float g_confrow[NROW];            // unweighted per-row focal sum (g/ln2)
__device__ float g_conf_part[8192];          // per-rs-block weighted conf (+corr)
__device__ float g_loc_part[8192];
__device__ int   g_npos_part[8192];

// ---------------- MUFU wrappers ------------------------------------------------
__device__ __forceinline__ float tanhf_a(float x) {
    float r;
    asm("tanh.approx.f32 %0, %1;" : "=f"(r) : "f"(x));
    return r;
}
__device__ __forceinline__ float lg2f(float x) {
    float r;
    asm("lg2.approx.f32 %0, %1;" : "=f"(r) : "f"(x));
    return r;
}

// 2-MUFU focal core: returns g(x)/ln2 where g(x) = sigmoid(x)^2 * softplus(x)
__device__ __forceinline__ float gfun_t(float x) {
    float T = tanhf_a(0.5f * x);
    float s = fmaf(0.5f, T, 0.5f);
    float u = fmaf(-0.5f, T, 0.5f);
    float L = lg2f(u);
    return -(s * s) * L;
}

__device__ __forceinline__ float sl1(float d) {
    float ad = fabsf(d);
    return (ad < 1.0f) ? 0.5f * d * d : ad - 0.5f;
}

// -------- IoU: textually identical arithmetic in all matching paths -----------
__device__ __forceinline__ float iou_fn(float px1, float py1, float px2, float py2,
                                        float parea, float4 bx) {
    float ltx = fmaxf(px1, bx.x), lty = fmaxf(py1, bx.y);
    float rbx = fminf(px2, bx.z), rby = fminf(py2, bx.w);
    float iw = fmaxf(rbx - ltx, 0.0f), ih = fmaxf(rby - lty, 0.0f);
    float inter = iw * ih;
    float ab = (bx.z - bx.x) * (bx.w - bx.y);
    return __fdividef(inter, parea + ab - inter);
}

// per-prior argmax over the 32 objects of one image (identical in rs + final)
__device__ __forceinline__ void prior_match(float4 pc, const float4* bx4,
                                            float& best, int& besto) {
    float hx = 0.5f * pc.z, hy = 0.5f * pc.w;
    float px1 = pc.x - hx, py1 = pc.y - hy;
    float px2 = pc.x + hx, py2 = pc.y + hy;
    float parea = (px2 - px1) * (py2 - py1);
    best = -1.0f; besto = 0;
    #pragma unroll 8
    for (int o = 0; o < NOBJ; o++) {
        float iou = iou_fn(px1, py1, px2, py2, parea, bx4[o]);
        if (iou > best) { best = iou; besto = o; }   // strict > => first-max
    }
}

// positive-row extras: focal correction + smooth-L1 loc (identical in rs + final)
__device__ __forceinline__ void pos_extras(const float* pscores, const float* plocs,
                                           int row, int t, float4 bx, float4 pc,
                                           float& corr, float& loc) {
    const float LN2 = 0.6931471805599453f;
    float xk = pscores[(size_t)row * NCLS + (t - 1)];
    corr = LN2 * (0.25f * gfun_t(-xk) - 0.75f * gfun_t(xk));
    float cx = 0.5f * (bx.x + bx.z), cy = 0.5f * (bx.y + bx.w);
    float w2 = bx.z - bx.x,          h2 = bx.w - bx.y;
    float g0 = __fdividef(cx - pc.x, 0.1f * pc.z);
    float g1 = __fdividef(cy - pc.y, 0.1f * pc.w);
    float g2 = 5.0f * __logf(__fdividef(w2, pc.z));
    float g3 = 5.0f * __logf(__fdividef(h2, pc.w));
    float4 pl = ((const float4*)plocs)[row];
    loc = sl1(pl.x - g0) + sl1(pl.y - g1) + sl1(pl.z - g2) + sl1(pl.w - g3);
}

// ======== MEGA: two fully independent block families (no ordering) ============
__global__ void __launch_bounds__(256)
k_mega(const float* __restrict__ plocs, const float* __restrict__ pscores,
       const float* __restrict__ boxes, const int* __restrict__ labels,
       const float* __restrict__ priors) {
    __shared__ float s_part[RS_E4];                 // rowsum staging (5 KB)
    __shared__ unsigned long long swk[8];

    if (blockIdx.x < OBJ_TOT) {
        // ---------------- per-object partial argmax over a prior chunk --------
        int idx = blockIdx.x;
        int o = idx & (NOBJ - 1);
        int b = (idx >> 5) & (BB - 1);
        int z = idx >> 9;
        float4 bx = ((const float4*)boxes)[b * NOBJ + o];

        int pr0 = z * OBJ_CHUNK;
        int pr1 = pr0 + OBJ_CHUNK;

        float best = 0.0f;          // only iou>0 can matter (key 0 = invalid)
        int   bestpr = -1;
        for (int pr = pr0 + threadIdx.x; pr < pr1; pr += 256) {
            float4 pc = ((const float4*)priors)[pr];
            float hx = 0.5f * pc.z, hy = 0.5f * pc.w;
            float px1 = pc.x - hx, py1 = pc.y - hy;
            float px2 = pc.x + hx, py2 = pc.y + hy;
            float parea = (px2 - px1) * (py2 - py1);
            float iou = iou_fn(px1, py1, px2, py2, parea, bx);
            if (iou > best) { best = iou; bestpr = pr; }   // strict > : smallest pr
        }
        unsigned long long key = 0ull;
        if (bestpr >= 0)
            key = (((unsigned long long)__float_as_uint(best)) << 32)
                | (unsigned long long)(0xFFFFFFFFu - (unsigned)bestpr);

        #pragma unroll
        for (int s = 16; s > 0; s >>= 1) {
            unsigned long long other = __shfl_xor_sync(0xFFFFFFFFu, key, s);
            if (other > key) key = other;
        }
        int lane = threadIdx.x & 31, wid = threadIdx.x >> 5;
        if (lane == 0) swk[wid] = key;
        __syncthreads();
        if (threadIdx.x == 0) {
            #pragma unroll
            for (int w = 1; w < 8; w++)
                if (swk[w] > key) key = swk[w];
            g_obj_part[idx] = key;
        }
    } else {
        // ------- rowsum + UNFORCED per-row matching + weighted partials -------
        const float SCALEF = 0.75f * 0.6931471805599453f;   // 0.75*ln2
        int rb = blockIdx.x - OBJ_TOT;
        const float4* sc4 = (const float4*)pscores;
        int base = rb * RS_E4;

        #pragma unroll
        for (int it = 0; it < RS_ITER; it++) {
            int l4 = it * 256 + threadIdx.x;
            float4 v = sc4[base + l4];
            float s4 = gfun_t(v.x) + gfun_t(v.y) + gfun_t(v.z) + gfun_t(v.w);
            s_part[l4] = s4;
        }
        __syncthreads();

        float conf = 0.0f, loc = 0.0f;
        int np = 0;

        if (threadIdx.x < RS_ROWS) {
            int row = rb * RS_ROWS + threadIdx.x;
            int b  = row / PP;
            int pr = row - b * PP;

            float rowconf = 0.0f;
            const float* p = &s_part[threadIdx.x * (NCLS / 4)];
            #pragma unroll
            for (int k = 0; k < NCLS / 4; k++) rowconf += p[k];
            g_confrow[row] = rowconf;

            float4 pc = ((const float4*)priors)[pr];
            const float4* bx4 = ((const float4*)boxes) + b * NOBJ;
            float best; int besto;
            prior_match(pc, bx4, best, besto);

            int t = 0;
            if (best >= 0.4f)
                t = (best < 0.5f) ? -1 : labels[b * NOBJ + besto];

            if (t >= 0) conf = SCALEF * rowconf;
            if (t > 0) {
                np = 1;
                float corr;
                pos_extras(pscores, plocs, row, t, bx4[besto], pc, corr, loc);
                conf += corr;
            }
        }

        #pragma unroll
        for (int s = 16; s > 0; s >>= 1) {
            conf += __shfl_xor_sync(0xFFFFFFFFu, conf, s);
            loc  += __shfl_xor_sync(0xFFFFFFFFu, loc, s);
            np   += __shfl_xor_sync(0xFFFFFFFFu, np, s);
        }
        __shared__ float swc[8], swl[8];
        __shared__ int   swn[8];
        int lane = threadIdx.x & 31, wid = threadIdx.x >> 5;
        if (lane == 0) { swc[wid] = conf; swl[wid] = loc; swn[wid] = np; }
        __syncthreads();
        if (threadIdx.x == 0) {
            float c = 0.0f, l = 0.0f; int n = 0;
            #pragma unroll
            for (int w = 0; w < 8; w++) { c += swc[w]; l += swl[w]; n += swn[w]; }
            g_conf_part[rb] = c;
            g_loc_part[rb]  = l;
            g_npos_part[rb] = n;
        }
    }
}

// ======== FINAL: forced-override delta corrections + total reduction ==========
__global__ void __launch_bounds__(256)
k_final(const float* __restrict__ plocs, const float* __restrict__ pscores,
        const float* __restrict__ boxes, const int* __restrict__ labels,
        const float* __restrict__ priors, float* __restrict__ out) {
    const float SCALEF = 0.75f * 0.6931471805599453f;
    __shared__ int   s_pr[NPAIR];
    __shared__ int   s_valid[NPAIR];
    __shared__ int   s_cnt[NPAIR];
    int tid = threadIdx.x;

    // 1) reduce the 8 per-split keys per (b,o) pair
    for (int i = tid; i < NPAIR; i += 256) {
        unsigned long long key = 0ull;
        #pragma unroll
        for (int z = 0; z < OBJ_SPLITS; z++) {
            unsigned long long k2 = g_obj_part[z * NPAIR + i];
            if (k2 > key) key = k2;
        }
        float ov = __uint_as_float((unsigned)(key >> 32));
        int valid = (ov > 0.0f) ? 1 : 0;
        s_valid[i] = valid;
        s_pr[i] = valid ? (int)(0xFFFFFFFFu - (unsigned)(key & 0xFFFFFFFFull)) : -1;
    }
    __syncthreads();

    // 2) filtered index per valid object (cumsum of valid within its image)
    for (int i = tid; i < NPAIR; i += 256) {
        int b0 = (i >> 5) << 5;   // image base
        int c = 0;
        for (int j = b0; j < i; j++) c += s_valid[j];
        s_cnt[i] = c;
    }
    __syncthreads();

    // 3) delta corrections (last-writer-wins per forced prior, per image)
    double dconf = 0.0, dloc = 0.0;
    int dnp = 0;
    for (int i = tid; i < NPAIR; i += 256) {
        if (!s_valid[i]) continue;
        int b  = i >> 5;
        int pr = s_pr[i];
        // skip if a later valid object of the same image targets the same prior
        bool last = true;
        for (int j = i + 1; j < ((b + 1) << 5); j++)
            if (s_valid[j] && s_pr[j] == pr) { last = false; break; }
        if (!last) continue;

        int row = b * PP + pr;
        float rowconf = g_confrow[row];
        float4 pc = ((const float4*)priors)[pr];
        const float4* bx4 = ((const float4*)boxes) + b * NOBJ;

        // --- old (unforced) contribution: identical arithmetic to rs path ---
        float best; int besto;
        prior_match(pc, bx4, best, besto);
        int t_old = 0;
        if (best >= 0.4f)
            t_old = (best < 0.5f) ? -1 : labels[b * NOBJ + besto];
        float conf_old = 0.0f, loc_old = 0.0f;
        int np_old = 0;
        if (t_old >= 0) conf_old = SCALEF * rowconf;
        if (t_old > 0) {
            np_old = 1;
            float corr_old;
            pos_extras(pscores, plocs, row, t_old, bx4[besto], pc, corr_old, loc_old);
            conf_old += corr_old;
        }

        // --- new (forced) contribution: ov=1.0, obj = filtered index ---------
        int objn = s_cnt[i];
        int t_new = labels[b * NOBJ + objn];          // labels >= 1 always
        float conf_new = SCALEF * rowconf;
        float corr_new, loc_new;
        pos_extras(pscores, plocs, row, t_new, bx4[objn], pc, corr_new, loc_new);
        conf_new += corr_new;

        dconf += (double)conf_new - (double)conf_old;
        dloc  += (double)loc_new  - (double)loc_old;
        dnp   += 1 - np_old;
    }

    // 4) reduce rs partials + deltas (deterministic)
    double c = dconf, l = dloc;
    int n = dnp;
    for (int i = tid; i < RS_BLOCKS; i += 256) {
        c += (double)g_conf_part[i];
        l += (double)g_loc_part[i];
        n += g_npos_part[i];
    }
    __shared__ double sc[256];
    __shared__ double sl[256];
    __shared__ int    sn[256];
    sc[tid] = c; sl[tid] = l; sn[tid] = n;
    __syncthreads();
    #pragma unroll
    for (int s = 128; s > 0; s >>= 1) {
        if (tid < s) {
            sc[tid] += sc[tid + s];
            sl[tid] += sl[tid + s];
            sn[tid] += sn[tid + s];
        }
        __syncthreads();
    }
    if (tid == 0) {
        double npos = (double)(sn[0] > 1 ? sn[0] : 1);
        out[0] = (float)(sc[0] / npos + sl[0] / (npos * 4.0));
    }
}

// ---------------- launch ---------------------------------------------------------
extern "C" void kernel_launch(void* const* d_in, const int* in_sizes, int n_in,
                              void* d_out, int out_size) {
    const float* plocs   = (const float*)d_in[0];
    const float* pscores = (const float*)d_in[1];
    const float* boxes   = (const float*)d_in[2];
    const int*   labels  = (const int*)d_in[3];
    const float* priors  = (const float*)d_in[4];
    float* out = (float*)d_out;

    k_mega<<<MEGA_BLOCKS, 256>>>(plocs, pscores, boxes, labels, priors);
    k_final<<<1, 256>>>(plocs, pscores, boxes, labels, priors, out);
}

// round 12
// speedup vs baseline: 1.1261x; 1.1261x over previous
#include <cuda_runtime.h>
#include <cstdint>
#include <cstddef>

#define BB   16
#define PP   22536
#define NOBJ 32
#define NCLS 80
#define NROW (BB * PP)                       // 360,576
#define NE4  (NROW * (NCLS / 4))             // 7,211,520 float4 elements

#define OBJ_SPLITS 8
#define OBJ_CHUNK  (PP / OBJ_SPLITS)         // 2817 exactly
#define OBJ_TOT    (BB * NOBJ * OBJ_SPLITS)  // 4096 blocks

#define RS_ITER    5
#define RS_E4      (256 * RS_ITER)           // 1280 e4 per block = 64 rows exactly
#define RS_ROWS    64
#define RS_BLOCKS  (NE4 / RS_E4)             // 5634 exactly

#define MEGA_BLOCKS (OBJ_TOT + RS_BLOCKS)    // 9730
#define NPAIR (BB * NOBJ)                    // 512

#define RED_BLOCKS ((RS_BLOCKS + 255) / 256) // 23
#define RED_TOT    (RED_BLOCKS + 1)          // 24 (last block = delta corrections)

// ---------------- persistent device scratch (no allocs allowed) ---------------
__device__ unsigned long long g_obj_part[OBJ_TOT];   // partial keys, idx z*512 + b*32 + o
__device__ float g_confrow[NROW];            // unweighted per-row focal sum (g/ln2)
__device__ float g_conf_part[8192];          // per-rs-block weighted conf (+corr)
__device__ float g_loc_part[8192];
__device__ int   g_npos_part[8192];
__device__ double g_red_c[RED_TOT];
__device__ double g_red_l[RED_TOT];
__device__ int    g_red_n[RED_TOT];

// ---------------- MUFU wrappers ------------------------------------------------
__device__ __forceinline__ float tanhf_a(float x) {
    float r;
    asm("tanh.approx.f32 %0, %1;" : "=f"(r) : "f"(x));
    return r;
}
__device__ __forceinline__ float lg2f(float x) {
    float r;
    asm("lg2.approx.f32 %0, %1;" : "=f"(r) : "f"(x));
    return r;
}

// 2-MUFU focal core: returns g(x)/ln2 where g(x) = sigmoid(x)^2 * softplus(x)
__device__ __forceinline__ float gfun_t(float x) {
    float T = tanhf_a(0.5f * x);
    float s = fmaf(0.5f, T, 0.5f);
    float u = fmaf(-0.5f, T, 0.5f);
    float L = lg2f(u);
    return -(s * s) * L;
}

__device__ __forceinline__ float sl1(float d) {
    float ad = fabsf(d);
    return (ad < 1.0f) ? 0.5f * d * d : ad - 0.5f;
}

// -------- IoU: textually identical arithmetic in all matching paths -----------
__device__ __forceinline__ float iou_fn(float px1, float py1, float px2, float py2,
                                        float parea, float4 bx) {
    float ltx = fmaxf(px1, bx.x), lty = fmaxf(py1, bx.y);
    float rbx = fminf(px2, bx.z), rby = fminf(py2, bx.w);
    float iw = fmaxf(rbx - ltx, 0.0f), ih = fmaxf(rby - lty, 0.0f);
    float inter = iw * ih;
    float ab = (bx.z - bx.x) * (bx.w - bx.y);
    return __fdividef(inter, parea + ab - inter);
}

// per-prior argmax over the 32 objects of one image (identical in rs + delta)
__device__ __forceinline__ void prior_match(float4 pc, const float4* bx4,
                                            float& best, int& besto) {
    float hx = 0.5f * pc.z, hy = 0.5f * pc.w;
    float px1 = pc.x - hx, py1 = pc.y - hy;
    float px2 = pc.x + hx, py2 = pc.y + hy;
    float parea = (px2 - px1) * (py2 - py1);
    best = -1.0f; besto = 0;
    #pragma unroll 8
    for (int o = 0; o < NOBJ; o++) {
        float iou = iou_fn(px1, py1, px2, py2, parea, bx4[o]);
        if (iou > best) { best = iou; besto = o; }   // strict > => first-max
    }
}

// positive-row extras: focal correction + smooth-L1 loc (identical in rs + delta)
__device__ __forceinline__ void pos_extras(const float* pscores, const float* plocs,
                                           int row, int t, float4 bx, float4 pc,
                                           float& corr, float& loc) {
    const float LN2 = 0.6931471805599453f;
    float xk = pscores[(size_t)row * NCLS + (t - 1)];
    corr = LN2 * (0.25f * gfun_t(-xk) - 0.75f * gfun_t(xk));
    float cx = 0.5f * (bx.x + bx.z), cy = 0.5f * (bx.y + bx.w);
    float w2 = bx.z - bx.x,          h2 = bx.w - bx.y;
    float g0 = __fdividef(cx - pc.x, 0.1f * pc.z);
    float g1 = __fdividef(cy - pc.y, 0.1f * pc.w);
    float g2 = 5.0f * __logf(__fdividef(w2, pc.z));
    float g3 = 5.0f * __logf(__fdividef(h2, pc.w));
    float4 pl = ((const float4*)plocs)[row];
    loc = sl1(pl.x - g0) + sl1(pl.y - g1) + sl1(pl.z - g2) + sl1(pl.w - g3);
}

// ======== MEGA: two fully independent block families (no ordering) ============
__global__ void __launch_bounds__(256)
k_mega(const float* __restrict__ plocs, const float* __restrict__ pscores,
       const float* __restrict__ boxes, const int* __restrict__ labels,
       const float* __restrict__ priors) {
    __shared__ float s_part[RS_E4];                 // rowsum staging (5 KB)
    __shared__ unsigned long long swk[8];

    if (blockIdx.x < OBJ_TOT) {
        // ---------------- per-object partial argmax over a prior chunk --------
        int idx = blockIdx.x;
        int o = idx & (NOBJ - 1);
        int b = (idx >> 5) & (BB - 1);
        int z = idx >> 9;
        float4 bx = ((const float4*)boxes)[b * NOBJ + o];

        int pr0 = z * OBJ_CHUNK;
        int pr1 = pr0 + OBJ_CHUNK;

        float best = 0.0f;          // only iou>0 can matter (key 0 = invalid)
        int   bestpr = -1;
        for (int pr = pr0 + threadIdx.x; pr < pr1; pr += 256) {
            float4 pc = ((const float4*)priors)[pr];
            float hx = 0.5f * pc.z, hy = 0.5f * pc.w;
            float px1 = pc.x - hx, py1 = pc.y - hy;
            float px2 = pc.x + hx, py2 = pc.y + hy;
            float parea = (px2 - px1) * (py2 - py1);
            float iou = iou_fn(px1, py1, px2, py2, parea, bx);
            if (iou > best) { best = iou; bestpr = pr; }   // strict > : smallest pr
        }
        unsigned long long key = 0ull;
        if (bestpr >= 0)
            key = (((unsigned long long)__float_as_uint(best)) << 32)
                | (unsigned long long)(0xFFFFFFFFu - (unsigned)bestpr);

        #pragma unroll
        for (int s = 16; s > 0; s >>= 1) {
            unsigned long long other = __shfl_xor_sync(0xFFFFFFFFu, key, s);
            if (other > key) key = other;
        }
        int lane = threadIdx.x & 31, wid = threadIdx.x >> 5;
        if (lane == 0) swk[wid] = key;
        __syncthreads();
        if (threadIdx.x == 0) {
            #pragma unroll
            for (int w = 1; w < 8; w++)
                if (swk[w] > key) key = swk[w];
            g_obj_part[idx] = key;
        }
    } else {
        // ------- rowsum + UNFORCED per-row matching + weighted partials -------
        const float SCALEF = 0.75f * 0.6931471805599453f;   // 0.75*ln2
        int rb = blockIdx.x - OBJ_TOT;
        const float4* sc4 = (const float4*)pscores;
        int base = rb * RS_E4;

        #pragma unroll
        for (int it = 0; it < RS_ITER; it++) {
            int l4 = it * 256 + threadIdx.x;
            float4 v = sc4[base + l4];
            float s4 = gfun_t(v.x) + gfun_t(v.y) + gfun_t(v.z) + gfun_t(v.w);
            s_part[l4] = s4;
        }
        __syncthreads();

        float conf = 0.0f, loc = 0.0f;
        int np = 0;

        if (threadIdx.x < RS_ROWS) {
            int row = rb * RS_ROWS + threadIdx.x;
            int b  = row / PP;
            int pr = row - b * PP;

            float rowconf = 0.0f;
            const float* p = &s_part[threadIdx.x * (NCLS / 4)];
            #pragma unroll
            for (int k = 0; k < NCLS / 4; k++) rowconf += p[k];
            g_confrow[row] = rowconf;

            float4 pc = ((const float4*)priors)[pr];
            const float4* bx4 = ((const float4*)boxes) + b * NOBJ;
            float best; int besto;
            prior_match(pc, bx4, best, besto);

            int t = 0;
            if (best >= 0.4f)
                t = (best < 0.5f) ? -1 : labels[b * NOBJ + besto];

            if (t >= 0) conf = SCALEF * rowconf;
            if (t > 0) {
                np = 1;
                float corr;
                pos_extras(pscores, plocs, row, t, bx4[besto], pc, corr, loc);
                conf += corr;
            }
        }

        #pragma unroll
        for (int s = 16; s > 0; s >>= 1) {
            conf += __shfl_xor_sync(0xFFFFFFFFu, conf, s);
            loc  += __shfl_xor_sync(0xFFFFFFFFu, loc, s);
            np   += __shfl_xor_sync(0xFFFFFFFFu, np, s);
        }
        __shared__ float swc[8], swl[8];
        __shared__ int   swn[8];
        int lane = threadIdx.x & 31, wid = threadIdx.x >> 5;
        if (lane == 0) { swc[wid] = conf; swl[wid] = loc; swn[wid] = np; }
        __syncthreads();
        if (threadIdx.x == 0) {
            float c = 0.0f, l = 0.0f; int n = 0;
            #pragma unroll
            for (int w = 0; w < 8; w++) { c += swc[w]; l += swl[w]; n += swn[w]; }
            g_conf_part[rb] = c;
            g_loc_part[rb]  = l;
            g_npos_part[rb] = n;
        }
    }
}

// ======== RED: parallel partial reduction + (one block) forced deltas =========
__global__ void __launch_bounds__(256)
k_red(const float* __restrict__ plocs, const float* __restrict__ pscores,
      const float* __restrict__ boxes, const int* __restrict__ labels,
      const float* __restrict__ priors) {
    __shared__ double sc[256];
    __shared__ double sl[256];
    __shared__ int    sn[256];
    int tid = threadIdx.x;

    if (blockIdx.x < RED_BLOCKS) {
        // ---- tree-reduce one slice of 256 rs partials ------------------------
        int i = blockIdx.x * 256 + tid;
        double c = 0.0, l = 0.0;
        int n = 0;
        if (i < RS_BLOCKS) {
            c = (double)g_conf_part[i];
            l = (double)g_loc_part[i];
            n = g_npos_part[i];
        }
        sc[tid] = c; sl[tid] = l; sn[tid] = n;
        __syncthreads();
        #pragma unroll
        for (int s = 128; s > 0; s >>= 1) {
            if (tid < s) {
                sc[tid] += sc[tid + s];
                sl[tid] += sl[tid + s];
                sn[tid] += sn[tid + s];
            }
            __syncthreads();
        }
        if (tid == 0) {
            g_red_c[blockIdx.x] = sc[0];
            g_red_l[blockIdx.x] = sl[0];
            g_red_n[blockIdx.x] = sn[0];
        }
    } else {
        // ---- forced-override delta corrections -------------------------------
        const float SCALEF = 0.75f * 0.6931471805599453f;
        __shared__ int s_pr[NPAIR];
        __shared__ int s_valid[NPAIR];
        __shared__ int s_cnt[NPAIR];

        for (int i = tid; i < NPAIR; i += 256) {
            unsigned long long key = 0ull;
            #pragma unroll
            for (int z = 0; z < OBJ_SPLITS; z++) {
                unsigned long long k2 = g_obj_part[z * NPAIR + i];
                if (k2 > key) key = k2;
            }
            float ov = __uint_as_float((unsigned)(key >> 32));
            int valid = (ov > 0.0f) ? 1 : 0;
            s_valid[i] = valid;
            s_pr[i] = valid ? (int)(0xFFFFFFFFu - (unsigned)(key & 0xFFFFFFFFull)) : -1;
        }
        __syncthreads();

        for (int i = tid; i < NPAIR; i += 256) {
            int b0 = (i >> 5) << 5;   // image base
            int c = 0;
            for (int j = b0; j < i; j++) c += s_valid[j];
            s_cnt[i] = c;
        }
        __syncthreads();

        double dconf = 0.0, dloc = 0.0;
        int dnp = 0;
        for (int i = tid; i < NPAIR; i += 256) {
            if (!s_valid[i]) continue;
            int b  = i >> 5;
            int pr = s_pr[i];
            // last-writer-wins on duplicate forced targets within an image
            bool last = true;
            for (int j = i + 1; j < ((b + 1) << 5); j++)
                if (s_valid[j] && s_pr[j] == pr) { last = false; break; }
            if (!last) continue;

            int row = b * PP + pr;
            float rowconf = g_confrow[row];
            float4 pc = ((const float4*)priors)[pr];
            const float4* bx4 = ((const float4*)boxes) + b * NOBJ;

            // old (unforced) contribution — identical arithmetic to rs path
            float best; int besto;
            prior_match(pc, bx4, best, besto);
            int t_old = 0;
            if (best >= 0.4f)
                t_old = (best < 0.5f) ? -1 : labels[b * NOBJ + besto];
            float conf_old = 0.0f, loc_old = 0.0f;
            int np_old = 0;
            if (t_old >= 0) conf_old = SCALEF * rowconf;
            if (t_old > 0) {
                np_old = 1;
                float corr_old;
                pos_extras(pscores, plocs, row, t_old, bx4[besto], pc, corr_old, loc_old);
                conf_old += corr_old;
            }

            // new (forced): ov=1.0, obj = filtered index
            int objn = s_cnt[i];
            int t_new = labels[b * NOBJ + objn];          // labels >= 1 always
            float conf_new = SCALEF * rowconf;
            float corr_new, loc_new;
            pos_extras(pscores, plocs, row, t_new, bx4[objn], pc, corr_new, loc_new);
            conf_new += corr_new;

            dconf += (double)conf_new - (double)conf_old;
            dloc  += (double)loc_new  - (double)loc_old;
            dnp   += 1 - np_old;
        }

        sc[tid] = dconf; sl[tid] = dloc; sn[tid] = dnp;
        __syncthreads();
        #pragma unroll
        for (int s = 128; s > 0; s >>= 1) {
            if (tid < s) {
                sc[tid] += sc[tid + s];
                sl[tid] += sl[tid + s];
                sn[tid] += sn[tid + s];
            }
            __syncthreads();
        }
        if (tid == 0) {
            g_red_c[RED_BLOCKS] = sc[0];
            g_red_l[RED_BLOCKS] = sl[0];
            g_red_n[RED_BLOCKS] = sn[0];
        }
    }
}

// ======== FIN: tiny deterministic final sum ===================================
__global__ void k_fin(float* __restrict__ out) {
    if (threadIdx.x == 0) {
        double c = 0.0, l = 0.0;
        int n = 0;
        #pragma unroll
        for (int i = 0; i < RED_TOT; i++) {
            c += g_red_c[i];
            l += g_red_l[i];
            n += g_red_n[i];
        }
        double npos = (double)(n > 1 ? n : 1);
        out[0] = (float)(c / npos + l / (npos * 4.0));
    }
}

// ---------------- launch ---------------------------------------------------------
extern "C" void kernel_launch(void* const* d_in, const int* in_sizes, int n_in,
                              void* d_out, int out_size) {
    const float* plocs   = (const float*)d_in[0];
    const float* pscores = (const float*)d_in[1];
    const float* boxes   = (const float*)d_in[2];
    const int*   labels  = (const int*)d_in[3];
    const float* priors  = (const float*)d_in[4];
    float* out = (float*)d_out;

    k_mega<<<MEGA_BLOCKS, 256>>>(plocs, pscores, boxes, labels, priors);
    k_red<<<RED_TOT, 256>>>(plocs, pscores, boxes, labels, priors);
    k_fin<<<1, 32>>>(out);
}

// round 13
// speedup vs baseline: 4.2222x; 3.7494x over previous
#include <cuda_runtime.h>
#include <cstdint>
#include <cstddef>

#define BB   16
#define PP   22536
#define NOBJ 32
#define NCLS 80
#define NROW (BB * PP)                       // 360,576
#define NE4  (NROW * (NCLS / 4))             // 7,211,520 float4 elements

#define OBJ_SPLITS 8
#define OBJ_CHUNK  (PP / OBJ_SPLITS)         // 2817 exactly
#define OBJ_TOT    (BB * NOBJ * OBJ_SPLITS)  // 4096 blocks

#define RS_ITER    5
#define RS_E4      (256 * RS_ITER)           // 1280 e4 per block = 64 rows exactly
#define RS_ROWS    64
#define RS_BLOCKS  (NE4 / RS_E4)             // 5634 exactly
#define MEGA_BLOCKS (OBJ_TOT + RS_BLOCKS)    // 9730

#define FUSED_GX  ((PP + 255) / 256)         // 89
#define FUSED_BLOCKS (FUSED_GX * BB)         // 1424

// ---------------- persistent device scratch (no allocs allowed) ---------------
__device__ unsigned long long g_obj_part[OBJ_TOT];   // partial keys, idx z*512 + b*32 + o
__device__ float g_confrow[NROW];            // unweighted per-row focal sum (g/ln2)
__device__ float g_conf_part[2048];          // per-fused-block conf (incl. corrections)
__device__ float g_loc_part[2048];
__device__ int   g_npos_part[2048];
__device__ unsigned g_done;

// ---------------- MUFU wrappers ------------------------------------------------
__device__ __forceinline__ float tanhf_a(float x) {
    float r;
    asm("tanh.approx.f32 %0, %1;" : "=f"(r) : "f"(x));
    return r;
}
__device__ __forceinline__ float lg2f(float x) {
    float r;
    asm("lg2.approx.f32 %0, %1;" : "=f"(r) : "f"(x));
    return r;
}

// 2-MUFU focal core: returns g(x)/ln2 where g(x) = sigmoid(x)^2 * softplus(x)
__device__ __forceinline__ float gfun_t(float x) {
    float T = tanhf_a(0.5f * x);
    float s = fmaf(0.5f, T, 0.5f);
    float u = fmaf(-0.5f, T, 0.5f);
    float L = lg2f(u);
    return -(s * s) * L;
}

__device__ __forceinline__ float sl1(float d) {
    float ad = fabsf(d);
    return (ad < 1.0f) ? 0.5f * d * d : ad - 0.5f;
}

// -------- IoU: textually identical arithmetic in all matching paths -----------
__device__ __forceinline__ float iou_fn(float px1, float py1, float px2, float py2,
                                        float parea, float4 bx) {
    float ltx = fmaxf(px1, bx.x), lty = fmaxf(py1, bx.y);
    float rbx = fminf(px2, bx.z), rby = fminf(py2, bx.w);
    float iw = fmaxf(rbx - ltx, 0.0f), ih = fmaxf(rby - lty, 0.0f);
    float inter = iw * ih;
    float ab = (bx.z - bx.x) * (bx.w - bx.y);
    return __fdividef(inter, parea + ab - inter);
}

// ======== MEGA (identical to R9's 37.2us version): obj argmax + rowsum ========
__global__ void __launch_bounds__(256)
k_mega(const float* __restrict__ pscores,
       const float* __restrict__ boxes, const float* __restrict__ priors) {
    __shared__ float s_part[RS_E4];                 // rowsum staging (5 KB)
    __shared__ unsigned long long swk[8];

    // deterministic counter reset for k_fused's amLast reduction
    if (blockIdx.x == 0 && threadIdx.x == 0) g_done = 0u;

    if (blockIdx.x < OBJ_TOT) {
        // ---------------- per-object partial argmax over a prior chunk --------
        int idx = blockIdx.x;
        int o = idx & (NOBJ - 1);
        int b = (idx >> 5) & (BB - 1);
        int z = idx >> 9;
        float4 bx = ((const float4*)boxes)[b * NOBJ + o];

        int pr0 = z * OBJ_CHUNK;
        int pr1 = pr0 + OBJ_CHUNK;

        float best = 0.0f;          // only iou>0 can matter (key 0 = invalid)
        int   bestpr = -1;
        for (int pr = pr0 + threadIdx.x; pr < pr1; pr += 256) {
            float4 pc = ((const float4*)priors)[pr];
            float hx = 0.5f * pc.z, hy = 0.5f * pc.w;
            float px1 = pc.x - hx, py1 = pc.y - hy;
            float px2 = pc.x + hx, py2 = pc.y + hy;
            float parea = (px2 - px1) * (py2 - py1);
            float iou = iou_fn(px1, py1, px2, py2, parea, bx);
            if (iou > best) { best = iou; bestpr = pr; }   // strict > : smallest pr
        }
        unsigned long long key = 0ull;
        if (bestpr >= 0)
            key = (((unsigned long long)__float_as_uint(best)) << 32)
                | (unsigned long long)(0xFFFFFFFFu - (unsigned)bestpr);

        #pragma unroll
        for (int s = 16; s > 0; s >>= 1) {
            unsigned long long other = __shfl_xor_sync(0xFFFFFFFFu, key, s);
            if (other > key) key = other;
        }
        int lane = threadIdx.x & 31, wid = threadIdx.x >> 5;
        if (lane == 0) swk[wid] = key;
        __syncthreads();
        if (threadIdx.x == 0) {
            #pragma unroll
            for (int w = 1; w < 8; w++)
                if (swk[w] > key) key = swk[w];
            g_obj_part[idx] = key;
        }
    } else {
        // ---------------- unweighted per-row focal sums (coalesced) -----------
        int rb = blockIdx.x - OBJ_TOT;
        const float4* sc4 = (const float4*)pscores;
        int base = rb * RS_E4;

        #pragma unroll
        for (int it = 0; it < RS_ITER; it++) {
            int l4 = it * 256 + threadIdx.x;
            float4 v = sc4[base + l4];
            float s4 = gfun_t(v.x) + gfun_t(v.y) + gfun_t(v.z) + gfun_t(v.w);
            s_part[l4] = s4;
        }
        __syncthreads();
        if (threadIdx.x < RS_ROWS) {
            const float* p = &s_part[threadIdx.x * (NCLS / 4)];
            float s = 0.0f;
            #pragma unroll
            for (int k = 0; k < NCLS / 4; k++) s += p[k];
            g_confrow[rb * RS_ROWS + threadIdx.x] = s;
        }
    }
}

// ======== FUSED: matching + override + weighted conf + loc + final ============
__global__ void __launch_bounds__(256)
k_fused(const float* __restrict__ plocs, const float* __restrict__ pscores,
        const float* __restrict__ boxes, const int* __restrict__ labels,
        const float* __restrict__ priors, float* __restrict__ out) {
    const float LN2 = 0.6931471805599453f;
    const float SCALEF = 0.75f * 0.6931471805599453f;   // 0.75*ln2
    int b  = blockIdx.y;
    int pr = blockIdx.x * blockDim.x + threadIdx.x;

    __shared__ float4 sbox[NOBJ];
    __shared__ int sprior[NOBJ];
    __shared__ int scnt[NOBJ];
    if (threadIdx.x < NOBJ) {
        sbox[threadIdx.x] = ((const float4*)boxes)[b * NOBJ + threadIdx.x];
        // reduce over splits: layout is idx = z*(BB*NOBJ) + b*NOBJ + o
        unsigned long long key = 0ull;
        #pragma unroll
        for (int z = 0; z < OBJ_SPLITS; z++) {
            unsigned long long k2 = g_obj_part[z * (BB * NOBJ) + b * NOBJ + threadIdx.x];
            if (k2 > key) key = k2;
        }
        float ovj = __uint_as_float((unsigned)(key >> 32));
        int valid = (ovj > 0.0f) ? 1 : 0;
        unsigned m = __ballot_sync(0xFFFFFFFFu, valid);
        sprior[threadIdx.x] = valid ? (int)(0xFFFFFFFFu - (unsigned)(key & 0xFFFFFFFFull)) : -1;
        scnt[threadIdx.x]   = __popc(m & ((1u << threadIdx.x) - 1u));
    }
    __syncthreads();

    float conf = 0.0f, loc = 0.0f;
    int np = 0;

    if (pr < PP) {
        float4 pc = ((const float4*)priors)[pr];
        float hx = 0.5f * pc.z, hy = 0.5f * pc.w;
        float px1 = pc.x - hx, py1 = pc.y - hy;
        float px2 = pc.x + hx, py2 = pc.y + hy;
        float parea = (px2 - px1) * (py2 - py1);

        float best = -1.0f;
        int   besto = 0;
        #pragma unroll 8
        for (int o = 0; o < NOBJ; o++) {
            float iou = iou_fn(px1, py1, px2, py2, parea, sbox[o]);
            if (iou > best) { best = iou; besto = o; }   // strict > => first-max
        }

        // forced override: ascending j, later valid objects overwrite (jax scatter)
        float ov = best;
        int obj = besto;
        #pragma unroll
        for (int j = 0; j < NOBJ; j++) {
            if (sprior[j] == pr) { ov = 1.0f; obj = scnt[j]; }
        }

        int t = 0;
        if (ov >= 0.4f)
            t = (ov < 0.5f) ? -1 : labels[b * NOBJ + obj];

        int row = b * PP + pr;
        if (t >= 0)
            conf = SCALEF * g_confrow[row];

        if (t > 0) {
            np = 1;
            float xk = pscores[(size_t)row * NCLS + (t - 1)];
            conf += LN2 * (0.25f * gfun_t(-xk) - 0.75f * gfun_t(xk));

            float4 bx  = sbox[obj];
            float cx = 0.5f * (bx.x + bx.z), cy = 0.5f * (bx.y + bx.w);
            float w2 = bx.z - bx.x,          h2 = bx.w - bx.y;
            float g0 = __fdividef(cx - pc.x, 0.1f * pc.z);
            float g1 = __fdividef(cy - pc.y, 0.1f * pc.w);
            float g2 = 5.0f * __logf(__fdividef(w2, pc.z));
            float g3 = 5.0f * __logf(__fdividef(h2, pc.w));
            float4 pl = ((const float4*)plocs)[row];
            loc = sl1(pl.x - g0) + sl1(pl.y - g1) + sl1(pl.z - g2) + sl1(pl.w - g3);
        }
    }

    #pragma unroll
    for (int s = 16; s > 0; s >>= 1) {
        conf += __shfl_xor_sync(0xFFFFFFFFu, conf, s);
        loc  += __shfl_xor_sync(0xFFFFFFFFu, loc, s);
        np   += __shfl_xor_sync(0xFFFFFFFFu, np, s);
    }
    __shared__ float swc[8], swl[8];
    __shared__ int   swn[8];
    int lane = threadIdx.x & 31, wid = threadIdx.x >> 5;
    if (lane == 0) { swc[wid] = conf; swl[wid] = loc; swn[wid] = np; }
    __syncthreads();

    __shared__ bool amLast;
    int cidx = blockIdx.y * gridDim.x + blockIdx.x;
    if (threadIdx.x == 0) {
        float c = 0.0f, l = 0.0f; int n = 0;
        #pragma unroll
        for (int w = 0; w < 8; w++) { c += swc[w]; l += swl[w]; n += swn[w]; }
        g_conf_part[cidx] = c;
        g_loc_part[cidx]  = l;
        g_npos_part[cidx] = n;
        __threadfence();
        unsigned v = atomicAdd(&g_done, 1u);
        amLast = (v == (unsigned)(FUSED_BLOCKS - 1));
    }
    __syncthreads();

    if (amLast) {
        __shared__ double sc[256];
        __shared__ double sl[256];
        __shared__ int    sn[256];
        int tid = threadIdx.x;
        double c = 0.0, l = 0.0;
        int n = 0;
        for (int i = tid; i < FUSED_BLOCKS; i += 256) {
            c += (double)g_conf_part[i];
            l += (double)g_loc_part[i];
            n += g_npos_part[i];
        }
        sc[tid] = c; sl[tid] = l; sn[tid] = n;
        __syncthreads();
        #pragma unroll
        for (int s = 128; s > 0; s >>= 1) {
            if (tid < s) {
                sc[tid] += sc[tid + s];
                sl[tid] += sl[tid + s];
                sn[tid] += sn[tid + s];
            }
            __syncthreads();
        }
        if (tid == 0) {
            double npos = (double)(sn[0] > 1 ? sn[0] : 1);
            out[0] = (float)(sc[0] / npos + sl[0] / (npos * 4.0));
        }
    }
}

// ---------------- launch ---------------------------------------------------------
extern "C" void kernel_launch(void* const* d_in, const int* in_sizes, int n_in,
                              void* d_out, int out_size) {
    const float* plocs   = (const float*)d_in[0];
    const float* pscores = (const float*)d_in[1];
    const float* boxes   = (const float*)d_in[2];
    const int*   labels  = (const int*)d_in[3];
    const float* priors  = (const float*)d_in[4];
    float* out = (float*)d_out;

    k_mega<<<MEGA_BLOCKS, 256>>>(pscores, boxes, priors);

    dim3 fg(FUSED_GX, BB);
    k_fused<<<fg, 256>>>(plocs, pscores, boxes, labels, priors, out);
}